// round 1
// baseline (speedup 1.0000x reference)
#include <cuda_runtime.h>
#include <cuda_bf16.h>
#include <cstdint>

// Problem constants
constexpr int Bb   = 2;
constexpr int T    = 2048;
constexpr int Cc   = 1024;
constexpr int H    = 16;
constexpr int D    = 64;
constexpr int HD   = H * D;          // 1024
constexpr int QKV3 = 3 * HD;         // 3072
constexpr int M_ROWS = Bb * T;       // 4096

// Scratch (no cudaMalloc allowed)
__device__ float g_qkv[(size_t)M_ROWS * QKV3];   // (B*T, 3072)
__device__ float g_attn[(size_t)M_ROWS * HD];    // (B*T, 1024)

// ---------------------------------------------------------------------------
// SGEMM: C[m][n] = sum_k A[m][k] * Bm[n][k] + bias[n]
// A: MxK row-major, Bm: NxK row-major (i.e. C = A @ Bm^T + bias)
// BM=BN=64, BK=16, 256 threads, 4x4 per thread.
// ---------------------------------------------------------------------------
__global__ __launch_bounds__(256) void sgemm_nt_bias(
    int M, int N, int K,
    const float* __restrict__ A,
    const float* __restrict__ Bm,
    const float* __restrict__ bias,
    float* __restrict__ C)
{
    constexpr int BM = 64, BN = 64, BK = 16;
    __shared__ float As[BK][BM];   // transposed: As[k][m]
    __shared__ float Bs[BK][BN];   // Bs[k][n]

    const int tid = threadIdx.x;
    const int tx  = tid & 15;      // 0..15 (n-direction)
    const int ty  = tid >> 4;      // 0..15 (m-direction)
    const int m0  = blockIdx.y * BM;
    const int n0  = blockIdx.x * BN;

    float acc[4][4];
#pragma unroll
    for (int i = 0; i < 4; i++)
#pragma unroll
        for (int j = 0; j < 4; j++) acc[i][j] = 0.f;

    const int lr  = tid >> 2;          // 0..63 row of tile
    const int lc4 = (tid & 3) << 2;    // 0,4,8,12 (k offset)

    for (int k0 = 0; k0 < K; k0 += BK) {
        {
            float4 v = *(const float4*)&A[(size_t)(m0 + lr) * K + k0 + lc4];
            As[lc4 + 0][lr] = v.x; As[lc4 + 1][lr] = v.y;
            As[lc4 + 2][lr] = v.z; As[lc4 + 3][lr] = v.w;
        }
        {
            float4 v = *(const float4*)&Bm[(size_t)(n0 + lr) * K + k0 + lc4];
            Bs[lc4 + 0][lr] = v.x; Bs[lc4 + 1][lr] = v.y;
            Bs[lc4 + 2][lr] = v.z; Bs[lc4 + 3][lr] = v.w;
        }
        __syncthreads();

#pragma unroll
        for (int k = 0; k < BK; k++) {
            float a[4], b[4];
#pragma unroll
            for (int i = 0; i < 4; i++) a[i] = As[k][ty * 4 + i];
#pragma unroll
            for (int j = 0; j < 4; j++) b[j] = Bs[k][tx * 4 + j];
#pragma unroll
            for (int i = 0; i < 4; i++)
#pragma unroll
                for (int j = 0; j < 4; j++)
                    acc[i][j] += a[i] * b[j];
        }
        __syncthreads();
    }

#pragma unroll
    for (int i = 0; i < 4; i++) {
        const int m = m0 + ty * 4 + i;
#pragma unroll
        for (int j = 0; j < 4; j++) {
            const int n = n0 + tx * 4 + j;
            C[(size_t)m * N + n] = acc[i][j] + bias[n];
        }
    }
}

// ---------------------------------------------------------------------------
// Flash attention with sink. One CTA per (q-tile of 64, head, batch).
// 256 threads; 4x4 register blocking for both QK^T and PV.
// qkv layout: (B*T, 3072) with q at [0,1024), k at [1024,2048), v at [2048,3072)
// ---------------------------------------------------------------------------
constexpr int SPAD = 68;   // padded row stride (floats), 16B-aligned, bank-safe
constexpr int ATTN_SMEM = 4 * 64 * SPAD * (int)sizeof(float);  // 69632 B

__global__ __launch_bounds__(256) void attn_kernel(
    const float* __restrict__ qkv,
    const float* __restrict__ sink_logit,
    float* __restrict__ attn_out)
{
    extern __shared__ float sm[];
    float (*QsT)[SPAD] = (float (*)[SPAD])(sm);                 // [d][row]
    float (*KsT)[SPAD] = (float (*)[SPAD])(sm + 64 * SPAD);     // [d][col]
    float (*Vs )[SPAD] = (float (*)[SPAD])(sm + 2 * 64 * SPAD); // [col][d]
    float (*PsT)[SPAD] = (float (*)[SPAD])(sm + 3 * 64 * SPAD); // [col][row]

    const int qt  = blockIdx.x;   // q tile (0..31)
    const int h   = blockIdx.y;
    const int b   = blockIdx.z;
    const int tid = threadIdx.x;
    const int tx  = tid & 15;     // col group
    const int ty  = tid >> 4;     // row group
    const int t0  = qt * 64;

    const float SC = 0.125f;      // 1/sqrt(64)

    // Load Q tile (scaled), transposed into QsT[d][row]
    for (int i = tid; i < 64 * 16; i += 256) {
        const int row = i >> 4;
        const int c4  = (i & 15) << 2;
        const float4 v = *(const float4*)&qkv[(size_t)(b * T + t0 + row) * QKV3 + h * D + c4];
        QsT[c4 + 0][row] = v.x * SC; QsT[c4 + 1][row] = v.y * SC;
        QsT[c4 + 2][row] = v.z * SC; QsT[c4 + 3][row] = v.w * SC;
    }

    const float sink = sink_logit[h];
    float m[4], l[4], acc[4][4];
#pragma unroll
    for (int i = 0; i < 4; i++) {
        m[i] = sink;   // sink slot: logit = sink, contributes exp(sink-m) to l
        l[i] = 1.0f;
#pragma unroll
        for (int j = 0; j < 4; j++) acc[i][j] = 0.f;
    }

    for (int kt = 0; kt <= qt; kt++) {
        const int k0 = kt * 64;
        // Load K (transposed) and V tiles
        for (int i = tid; i < 64 * 16; i += 256) {
            const int row = i >> 4;
            const int c4  = (i & 15) << 2;
            const size_t base = (size_t)(b * T + k0 + row) * QKV3 + h * D;
            const float4 kv = *(const float4*)&qkv[base + HD + c4];
            KsT[c4 + 0][row] = kv.x; KsT[c4 + 1][row] = kv.y;
            KsT[c4 + 2][row] = kv.z; KsT[c4 + 3][row] = kv.w;
            const float4 vv = *(const float4*)&qkv[base + 2 * HD + c4];
            *(float4*)&Vs[row][c4] = vv;
        }
        __syncthreads();

        // S = Q K^T (4x4 per thread)
        float s[4][4];
#pragma unroll
        for (int i = 0; i < 4; i++)
#pragma unroll
            for (int j = 0; j < 4; j++) s[i][j] = 0.f;

#pragma unroll 4
        for (int d = 0; d < 64; d++) {
            float a[4], bb[4];
#pragma unroll
            for (int i = 0; i < 4; i++) a[i]  = QsT[d][ty * 4 + i];
#pragma unroll
            for (int j = 0; j < 4; j++) bb[j] = KsT[d][tx * 4 + j];
#pragma unroll
            for (int i = 0; i < 4; i++)
#pragma unroll
                for (int j = 0; j < 4; j++)
                    s[i][j] += a[i] * bb[j];
        }

        if (kt == qt) {   // causal mask on diagonal tile
#pragma unroll
            for (int i = 0; i < 4; i++)
#pragma unroll
                for (int j = 0; j < 4; j++)
                    if (tx * 4 + j > ty * 4 + i) s[i][j] = -3.0e38f;
        }

        // Online softmax per row (rows replicated over the 16 tx lanes)
#pragma unroll
        for (int i = 0; i < 4; i++) {
            float rmax = s[i][0];
#pragma unroll
            for (int j = 1; j < 4; j++) rmax = fmaxf(rmax, s[i][j]);
#pragma unroll
            for (int off = 8; off >= 1; off >>= 1)
                rmax = fmaxf(rmax, __shfl_xor_sync(0xffffffffu, rmax, off));

            const float mnew = fmaxf(m[i], rmax);
            const float scl  = __expf(m[i] - mnew);
            float p[4], rsum = 0.f;
#pragma unroll
            for (int j = 0; j < 4; j++) {
                p[j] = __expf(s[i][j] - mnew);
                rsum += p[j];
            }
#pragma unroll
            for (int off = 8; off >= 1; off >>= 1)
                rsum += __shfl_xor_sync(0xffffffffu, rsum, off);

            l[i] = l[i] * scl + rsum;
            m[i] = mnew;
#pragma unroll
            for (int j = 0; j < 4; j++) {
                acc[i][j] *= scl;
                PsT[tx * 4 + j][ty * 4 + i] = p[j];
            }
        }
        __syncthreads();

        // acc += P @ V  (k-dim = column c)
#pragma unroll 4
        for (int c = 0; c < 64; c++) {
            float a[4], bb[4];
#pragma unroll
            for (int i = 0; i < 4; i++) a[i]  = PsT[c][ty * 4 + i];
#pragma unroll
            for (int j = 0; j < 4; j++) bb[j] = Vs[c][tx * 4 + j];
#pragma unroll
            for (int i = 0; i < 4; i++)
#pragma unroll
                for (int j = 0; j < 4; j++)
                    acc[i][j] += a[i] * bb[j];
        }
        __syncthreads();
    }

    // Epilogue: out[b, t, h*D + d] = acc / l
#pragma unroll
    for (int i = 0; i < 4; i++) {
        const float inv = 1.0f / l[i];
#pragma unroll
        for (int j = 0; j < 4; j++) {
            attn_out[(size_t)(b * T + t0 + ty * 4 + i) * HD + h * D + tx * 4 + j] =
                acc[i][j] * inv;
        }
    }
}

// ---------------------------------------------------------------------------
// Launch
// ---------------------------------------------------------------------------
extern "C" void kernel_launch(void* const* d_in, const int* in_sizes, int n_in,
                              void* d_out, int out_size)
{
    const float* x      = (const float*)d_in[0];
    const float* W_qkv  = (const float*)d_in[1];
    const float* b_qkv  = (const float*)d_in[2];
    const float* W_proj = (const float*)d_in[3];
    const float* b_proj = (const float*)d_in[4];
    const float* sink   = (const float*)d_in[5];
    float* out = (float*)d_out;

    float* qkvbuf  = nullptr;
    float* attnbuf = nullptr;
    cudaGetSymbolAddress((void**)&qkvbuf, g_qkv);
    cudaGetSymbolAddress((void**)&attnbuf, g_attn);

    cudaFuncSetAttribute(attn_kernel,
                         cudaFuncAttributeMaxDynamicSharedMemorySize, ATTN_SMEM);

    // 1) QKV GEMM: (4096,1024) @ (3072,1024)^T -> (4096,3072)
    sgemm_nt_bias<<<dim3(QKV3 / 64, M_ROWS / 64), 256>>>(
        M_ROWS, QKV3, Cc, x, W_qkv, b_qkv, qkvbuf);

    // 2) Flash attention with sink -> (4096,1024)
    attn_kernel<<<dim3(T / 64, H, Bb), 256, ATTN_SMEM>>>(qkvbuf, sink, attnbuf);

    // 3) Proj GEMM: (4096,1024) @ (1024,1024)^T + bias -> d_out
    sgemm_nt_bias<<<dim3(HD / 64, M_ROWS / 64), 256>>>(
        M_ROWS, HD, HD, attnbuf, W_proj, b_proj, out);
}

// round 2
// speedup vs baseline: 3.1416x; 3.1416x over previous
#include <cuda_runtime.h>
#include <cstdint>

// Problem constants
constexpr int Bb   = 2;
constexpr int T    = 2048;
constexpr int Cc   = 1024;
constexpr int H    = 16;
constexpr int D    = 64;
constexpr int HD   = H * D;          // 1024
constexpr int QKV3 = 3 * HD;         // 3072
constexpr int M_ROWS = Bb * T;       // 4096

// Scratch (no cudaMalloc allowed)
__device__ float g_qkv[(size_t)M_ROWS * QKV3];   // (B*T, 3072)
__device__ float g_attn[(size_t)M_ROWS * HD];    // (B*T, 1024)

// ---------------------------------------------------------------------------
// tf32 helpers
// ---------------------------------------------------------------------------
__device__ __forceinline__ uint32_t f2tf32(float x) {
    uint32_t r;
    asm("cvt.rna.tf32.f32 %0, %1;" : "=r"(r) : "f"(x));
    return r;
}

// D += A(16x8,row) * B(8x8,col)  tf32 inputs, f32 accum
__device__ __forceinline__ void mma8(float& d0, float& d1, float& d2, float& d3,
                                     uint32_t a0, uint32_t a1, uint32_t a2, uint32_t a3,
                                     uint32_t b0, uint32_t b1) {
    asm volatile(
        "mma.sync.aligned.m16n8k8.row.col.f32.tf32.tf32.f32 "
        "{%0,%1,%2,%3}, {%4,%5,%6,%7}, {%8,%9}, {%0,%1,%2,%3};\n"
        : "+f"(d0), "+f"(d1), "+f"(d2), "+f"(d3)
        : "r"(a0), "r"(a1), "r"(a2), "r"(a3), "r"(b0), "r"(b1));
}

// ---------------------------------------------------------------------------
// tf32 GEMM: C = A @ Bm^T + bias.  A: MxK row-major, Bm: NxK row-major.
// 128x128 tile, BK=16, 256 threads (8 warps, 2x4 over MxN).
// smem stride 20 words => frag LDS conflict-free (20 mod 32 = 20; see analysis).
// ---------------------------------------------------------------------------
constexpr int GS = 20;  // smem row stride in words

__global__ __launch_bounds__(256) void gemm_tf32(
    int M, int N, int K,
    const float* __restrict__ A,
    const float* __restrict__ Bm,
    const float* __restrict__ bias,
    float* __restrict__ C)
{
    __shared__ uint32_t As[128 * GS];
    __shared__ uint32_t Bs[128 * GS];

    const int tid  = threadIdx.x;
    const int lane = tid & 31;
    const int wid  = tid >> 5;
    const int wm   = (wid & 1) * 64;   // 2 warps in M, 64 rows each (4 m-tiles)
    const int wn   = (wid >> 1) * 32;  // 4 warps in N, 32 cols each (4 n-tiles)
    const int m0   = blockIdx.y * 128;
    const int n0   = blockIdx.x * 128;
    const int lr   = lane >> 2;        // 0..7
    const int lc   = lane & 3;         // 0..3

    float acc[4][4][4] = {};

    for (int k0 = 0; k0 < K; k0 += 16) {
#pragma unroll
        for (int p = 0; p < 2; p++) {
            const int f   = tid + p * 256;       // 0..511 float4 slots
            const int row = f >> 2;              // 0..127
            const int kc  = (f & 3) << 2;        // 0,4,8,12
            float4 va = *(const float4*)&A[(size_t)(m0 + row) * K + k0 + kc];
            uint32_t* da = &As[row * GS + kc];
            da[0] = f2tf32(va.x); da[1] = f2tf32(va.y);
            da[2] = f2tf32(va.z); da[3] = f2tf32(va.w);
            float4 vb = *(const float4*)&Bm[(size_t)(n0 + row) * K + k0 + kc];
            uint32_t* db = &Bs[row * GS + kc];
            db[0] = f2tf32(vb.x); db[1] = f2tf32(vb.y);
            db[2] = f2tf32(vb.z); db[3] = f2tf32(vb.w);
        }
        __syncthreads();

#pragma unroll
        for (int kk = 0; kk < 16; kk += 8) {
            uint32_t a[4][4], b[4][2];
#pragma unroll
            for (int i = 0; i < 4; i++) {
                const int r = wm + i * 16 + lr;
                const int c = kk + lc;
                a[i][0] = As[r * GS + c];
                a[i][1] = As[(r + 8) * GS + c];
                a[i][2] = As[r * GS + c + 4];
                a[i][3] = As[(r + 8) * GS + c + 4];
            }
#pragma unroll
            for (int j = 0; j < 4; j++) {
                const int n = wn + j * 8 + lr;
                b[j][0] = Bs[n * GS + kk + lc];
                b[j][1] = Bs[n * GS + kk + lc + 4];
            }
#pragma unroll
            for (int i = 0; i < 4; i++)
#pragma unroll
                for (int j = 0; j < 4; j++)
                    mma8(acc[i][j][0], acc[i][j][1], acc[i][j][2], acc[i][j][3],
                         a[i][0], a[i][1], a[i][2], a[i][3], b[j][0], b[j][1]);
        }
        __syncthreads();
    }

#pragma unroll
    for (int i = 0; i < 4; i++) {
        const int r = m0 + wm + i * 16 + lr;
#pragma unroll
        for (int j = 0; j < 4; j++) {
            const int c = n0 + wn + j * 8 + 2 * lc;
            const float2 bi = *(const float2*)&bias[c];
            float2 v0 = { acc[i][j][0] + bi.x, acc[i][j][1] + bi.y };
            *(float2*)&C[(size_t)r * N + c] = v0;
            float2 v1 = { acc[i][j][2] + bi.x, acc[i][j][3] + bi.y };
            *(float2*)&C[(size_t)(r + 8) * N + c] = v1;
        }
    }
}

// ---------------------------------------------------------------------------
// Flash attention (tf32 mma) with sink.
// One CTA per (64-row q tile, head, batch); 128 threads = 4 warps,
// each warp owns 16 q rows. Bc = 64.
// Smem strides: AS=68 (mod 32 = 4: conflict-free a/b frags over rows),
//               VS=72 (mod 32 = 8: conflict-free V b-frags over k).
// ---------------------------------------------------------------------------
constexpr int AS = 68;
constexpr int VS = 72;
constexpr int ATTN_SMEM = (3 * 64 * AS + 64 * VS) * (int)sizeof(uint32_t); // 70656 B

__global__ __launch_bounds__(128) void attn_tf32(
    const float* __restrict__ qkv,
    const float* __restrict__ sink_logit,
    float* __restrict__ attn_out)
{
    extern __shared__ uint32_t sm[];
    uint32_t* Qs = sm;                       // [64][AS]  q (scaled, tf32)
    uint32_t* Ks = sm + 64 * AS;             // [64][AS]  k
    uint32_t* Vs = sm + 2 * 64 * AS;         // [64][VS]  v (row = kv idx)
    uint32_t* Ps = sm + 2 * 64 * AS + 64 * VS; // [64][AS] probs

    const int qt  = blockIdx.x;
    const int h   = blockIdx.y;
    const int b   = blockIdx.z;
    const int tid = threadIdx.x;
    const int lane = tid & 31;
    const int wid  = tid >> 5;
    const int t0   = qt * 64;
    const int mb   = wid * 16;     // this warp's q-row base within tile
    const int lr   = lane >> 2;    // 0..7
    const int lc   = lane & 3;     // 0..3
    const float SC = 0.125f;       // 1/sqrt(64)

    // Load Q (scaled, tf32-rounded)
    for (int i = tid; i < 64 * 16; i += 128) {
        const int row = i >> 4;
        const int c4  = (i & 15) << 2;
        float4 v = *(const float4*)&qkv[(size_t)(b * T + t0 + row) * QKV3 + h * D + c4];
        uint32_t* d = &Qs[row * AS + c4];
        d[0] = f2tf32(v.x * SC); d[1] = f2tf32(v.y * SC);
        d[2] = f2tf32(v.z * SC); d[3] = f2tf32(v.w * SC);
    }

    const float sink = sink_logit[h];
    float m0 = sink, m1 = sink, l0 = 1.f, l1 = 1.f;
    float o[8][4] = {};   // [d-tile][c0..c3]; c0/c1 -> row lr, c2/c3 -> row lr+8

    for (int kt = 0; kt <= qt; kt++) {
        __syncthreads();   // previous iter's smem reads done (also covers Q load)
        const int k0 = kt * 64;
        for (int i = tid; i < 64 * 16; i += 128) {
            const int row = i >> 4;
            const int c4  = (i & 15) << 2;
            const size_t base = (size_t)(b * T + k0 + row) * QKV3 + h * D;
            float4 kv = *(const float4*)&qkv[base + HD + c4];
            uint32_t* dk = &Ks[row * AS + c4];
            dk[0] = f2tf32(kv.x); dk[1] = f2tf32(kv.y);
            dk[2] = f2tf32(kv.z); dk[3] = f2tf32(kv.w);
            float4 vv = *(const float4*)&qkv[base + 2 * HD + c4];
            uint32_t* dv = &Vs[row * VS + c4];
            dv[0] = f2tf32(vv.x); dv[1] = f2tf32(vv.y);
            dv[2] = f2tf32(vv.z); dv[3] = f2tf32(vv.w);
        }
        __syncthreads();

        // S = Q K^T : 8 n-tiles x 8 k-steps
        float s[8][4] = {};
#pragma unroll
        for (int kk = 0; kk < 64; kk += 8) {
            const uint32_t a0 = Qs[(mb + lr) * AS + kk + lc];
            const uint32_t a1 = Qs[(mb + 8 + lr) * AS + kk + lc];
            const uint32_t a2 = Qs[(mb + lr) * AS + kk + lc + 4];
            const uint32_t a3 = Qs[(mb + 8 + lr) * AS + kk + lc + 4];
#pragma unroll
            for (int j = 0; j < 8; j++) {
                const uint32_t b0 = Ks[(j * 8 + lr) * AS + kk + lc];
                const uint32_t b1 = Ks[(j * 8 + lr) * AS + kk + lc + 4];
                mma8(s[j][0], s[j][1], s[j][2], s[j][3], a0, a1, a2, a3, b0, b1);
            }
        }

        if (kt == qt) {    // causal mask on diagonal tile
            const int qr0 = mb + lr, qr1 = qr0 + 8;
#pragma unroll
            for (int j = 0; j < 8; j++) {
                const int c = j * 8 + 2 * lc;
                if (c     > qr0) s[j][0] = -1e30f;
                if (c + 1 > qr0) s[j][1] = -1e30f;
                if (c     > qr1) s[j][2] = -1e30f;
                if (c + 1 > qr1) s[j][3] = -1e30f;
            }
        }

        // Online softmax: rows lr (regs 0,1) and lr+8 (regs 2,3); quad reduce
        float rmax0 = -1e30f, rmax1 = -1e30f;
#pragma unroll
        for (int j = 0; j < 8; j++) {
            rmax0 = fmaxf(rmax0, fmaxf(s[j][0], s[j][1]));
            rmax1 = fmaxf(rmax1, fmaxf(s[j][2], s[j][3]));
        }
        rmax0 = fmaxf(rmax0, __shfl_xor_sync(~0u, rmax0, 1));
        rmax0 = fmaxf(rmax0, __shfl_xor_sync(~0u, rmax0, 2));
        rmax1 = fmaxf(rmax1, __shfl_xor_sync(~0u, rmax1, 1));
        rmax1 = fmaxf(rmax1, __shfl_xor_sync(~0u, rmax1, 2));

        const float mn0 = fmaxf(m0, rmax0), mn1 = fmaxf(m1, rmax1);
        const float sc0 = __expf(m0 - mn0), sc1 = __expf(m1 - mn1);
        float rs0 = 0.f, rs1 = 0.f;
#pragma unroll
        for (int j = 0; j < 8; j++) {
            s[j][0] = __expf(s[j][0] - mn0);
            s[j][1] = __expf(s[j][1] - mn0);
            s[j][2] = __expf(s[j][2] - mn1);
            s[j][3] = __expf(s[j][3] - mn1);
            rs0 += s[j][0] + s[j][1];
            rs1 += s[j][2] + s[j][3];
        }
        rs0 += __shfl_xor_sync(~0u, rs0, 1); rs0 += __shfl_xor_sync(~0u, rs0, 2);
        rs1 += __shfl_xor_sync(~0u, rs1, 1); rs1 += __shfl_xor_sync(~0u, rs1, 2);
        l0 = l0 * sc0 + rs0;  l1 = l1 * sc1 + rs1;
        m0 = mn0;  m1 = mn1;

#pragma unroll
        for (int j = 0; j < 8; j++) {
            o[j][0] *= sc0; o[j][1] *= sc0;
            o[j][2] *= sc1; o[j][3] *= sc1;
            const int c = j * 8 + 2 * lc;
            Ps[(mb + lr) * AS + c]         = f2tf32(s[j][0]);
            Ps[(mb + lr) * AS + c + 1]     = f2tf32(s[j][1]);
            Ps[(mb + 8 + lr) * AS + c]     = f2tf32(s[j][2]);
            Ps[(mb + 8 + lr) * AS + c + 1] = f2tf32(s[j][3]);
        }
        __syncwarp();   // P rows are warp-private; make stores visible to lanes

        // O += P @ V : A = P (rows = q, k = kv col), B = V[c][d] read col-major
#pragma unroll
        for (int cc = 0; cc < 64; cc += 8) {
            const uint32_t a0 = Ps[(mb + lr) * AS + cc + lc];
            const uint32_t a1 = Ps[(mb + 8 + lr) * AS + cc + lc];
            const uint32_t a2 = Ps[(mb + lr) * AS + cc + lc + 4];
            const uint32_t a3 = Ps[(mb + 8 + lr) * AS + cc + lc + 4];
#pragma unroll
            for (int j = 0; j < 8; j++) {
                const uint32_t b0 = Vs[(cc + lc) * VS + j * 8 + lr];
                const uint32_t b1 = Vs[(cc + lc + 4) * VS + j * 8 + lr];
                mma8(o[j][0], o[j][1], o[j][2], o[j][3], a0, a1, a2, a3, b0, b1);
            }
        }
    }

    // Epilogue
    const float inv0 = 1.f / l0, inv1 = 1.f / l1;
#pragma unroll
    for (int j = 0; j < 8; j++) {
        const int c = h * D + j * 8 + 2 * lc;
        float2 v0 = { o[j][0] * inv0, o[j][1] * inv0 };
        *(float2*)&attn_out[(size_t)(b * T + t0 + mb + lr) * HD + c] = v0;
        float2 v1 = { o[j][2] * inv1, o[j][3] * inv1 };
        *(float2*)&attn_out[(size_t)(b * T + t0 + mb + 8 + lr) * HD + c] = v1;
    }
}

// ---------------------------------------------------------------------------
// Launch
// ---------------------------------------------------------------------------
extern "C" void kernel_launch(void* const* d_in, const int* in_sizes, int n_in,
                              void* d_out, int out_size)
{
    const float* x      = (const float*)d_in[0];
    const float* W_qkv  = (const float*)d_in[1];
    const float* b_qkv  = (const float*)d_in[2];
    const float* W_proj = (const float*)d_in[3];
    const float* b_proj = (const float*)d_in[4];
    const float* sink   = (const float*)d_in[5];
    float* out = (float*)d_out;

    float* qkvbuf  = nullptr;
    float* attnbuf = nullptr;
    cudaGetSymbolAddress((void**)&qkvbuf, g_qkv);
    cudaGetSymbolAddress((void**)&attnbuf, g_attn);

    cudaFuncSetAttribute(attn_tf32,
                         cudaFuncAttributeMaxDynamicSharedMemorySize, ATTN_SMEM);

    // 1) QKV GEMM: (4096,1024) @ (3072,1024)^T -> (4096,3072)
    gemm_tf32<<<dim3(QKV3 / 128, M_ROWS / 128), 256>>>(
        M_ROWS, QKV3, Cc, x, W_qkv, b_qkv, qkvbuf);

    // 2) Flash attention with sink -> (4096,1024)
    attn_tf32<<<dim3(T / 64, H, Bb), 128, ATTN_SMEM>>>(qkvbuf, sink, attnbuf);

    // 3) Proj GEMM: (4096,1024) @ (1024,1024)^T + bias -> d_out
    gemm_tf32<<<dim3(HD / 128, M_ROWS / 128), 256>>>(
        M_ROWS, HD, HD, attnbuf, W_proj, b_proj, out);
}